// round 5
// baseline (speedup 1.0000x reference)
#include <cuda_runtime.h>
#include <cuda_bf16.h>
#include <math.h>

// Problem constants
#define DIMN      1024
#define NUM_HEADS 16
#define HEAD_DIM  64
#define BATCH     2
#define SEQ       2048
#define MROWS     (BATCH * SEQ)          // 4096
#define QK_SCALE  0.125f                 // 64^-0.5

// ---------------- scratch (static device globals; no allocation) -----------
__device__ float g_qh[BATCH * NUM_HEADS * SEQ * HEAD_DIM];   // [B,H,L,hd]
__device__ float g_kh[BATCH * NUM_HEADS * SEQ * HEAD_DIM];
__device__ float g_vh[BATCH * NUM_HEADS * SEQ * HEAD_DIM];
__device__ float g_attn[BATCH * SEQ * DIMN];                 // [B,L,D]

// ---------------------------------------------------------------------------
// GEMM: C = A[M,K] @ W[N,K]^T + bias[N]
// mode 0: store head-split to [B,H,L,hd]   (projections)
// mode 1: store flat [M,N]                 (output projection)
// BM=BN=128, BK=8, 256 threads, 8x8 per-thread microtile.
// M=4096, N=1024, K=1024 -> all tile-exact, no bounds checks.
// ---------------------------------------------------------------------------
#define BM 128
#define BN 128
#define BK 8

__global__ __launch_bounds__(256)
void gemm_bias_kernel(const float* __restrict__ A,
                      const float* __restrict__ W,
                      const float* __restrict__ bias,
                      float* __restrict__ C,
                      int M, int N, int K, int mode)
{
    __shared__ float As[BK][BM];
    __shared__ float Bs[BK][BN];

    const int tid = threadIdx.x;
    const int tx  = tid & 15;        // 0..15  (n)
    const int ty  = tid >> 4;        // 0..15  (m)
    const int m0  = blockIdx.y * BM;
    const int n0  = blockIdx.x * BN;

    // cooperative-load coordinates: 128 rows x 8 cols, one float4 per thread
    const int ldRow  = tid >> 1;            // 0..127
    const int ldCol4 = (tid & 1) << 2;      // 0 or 4

    float acc[8][8];
#pragma unroll
    for (int i = 0; i < 8; ++i)
#pragma unroll
        for (int j = 0; j < 8; ++j) acc[i][j] = 0.0f;

    const float* Aptr = A + (size_t)(m0 + ldRow) * K + ldCol4;
    const float* Wptr = W + (size_t)(n0 + ldRow) * K + ldCol4;

    for (int kt = 0; kt < K; kt += BK) {
        float4 av = *(const float4*)(Aptr + kt);
        float4 wv = *(const float4*)(Wptr + kt);
        As[ldCol4 + 0][ldRow] = av.x;
        As[ldCol4 + 1][ldRow] = av.y;
        As[ldCol4 + 2][ldRow] = av.z;
        As[ldCol4 + 3][ldRow] = av.w;
        Bs[ldCol4 + 0][ldRow] = wv.x;
        Bs[ldCol4 + 1][ldRow] = wv.y;
        Bs[ldCol4 + 2][ldRow] = wv.z;
        Bs[ldCol4 + 3][ldRow] = wv.w;
        __syncthreads();

#pragma unroll
        for (int kk = 0; kk < BK; ++kk) {
            float a[8], b[8];
            *(float4*)&a[0] = *(float4*)&As[kk][ty * 8];
            *(float4*)&a[4] = *(float4*)&As[kk][ty * 8 + 4];
            *(float4*)&b[0] = *(float4*)&Bs[kk][tx * 8];
            *(float4*)&b[4] = *(float4*)&Bs[kk][tx * 8 + 4];
#pragma unroll
            for (int i = 0; i < 8; ++i)
#pragma unroll
                for (int j = 0; j < 8; ++j)
                    acc[i][j] = fmaf(a[i], b[j], acc[i][j]);
        }
        __syncthreads();
    }

    // epilogue: bias + store (float4; 8-wide groups never cross a 64 boundary)
#pragma unroll
    for (int i = 0; i < 8; ++i) {
        const int m = m0 + ty * 8 + i;
#pragma unroll
        for (int jj = 0; jj < 8; jj += 4) {
            const int n = n0 + tx * 8 + jj;
            float4 bv = *(const float4*)&bias[n];
            float4 r;
            r.x = acc[i][jj + 0] + bv.x;
            r.y = acc[i][jj + 1] + bv.y;
            r.z = acc[i][jj + 2] + bv.z;
            r.w = acc[i][jj + 3] + bv.w;
            if (mode == 1) {
                *(float4*)&C[(size_t)m * N + n] = r;
            } else {
                const int b  = m >> 11;          // / SEQ
                const int l  = m & 2047;
                const int h  = n >> 6;           // / HEAD_DIM
                const int hd = n & 63;
                size_t dst = ((((size_t)b * NUM_HEADS + h) * SEQ + l) * HEAD_DIM + hd);
                *(float4*)&C[dst] = r;
            }
        }
    }
}

// ---------------------------------------------------------------------------
// Flash attention (fp32): grid (SEQ/128, B*H), 128 threads, 1 thread = 1 query.
// Q (pre-scaled) and O accumulator live in registers; K/V tiles (64 keys) in
// SMEM, read as broadcast float4. Online softmax with 16-key register chunks.
// ---------------------------------------------------------------------------
__global__ __launch_bounds__(128)
void attn_kernel(const float* __restrict__ Qh,
                 const float* __restrict__ Kh,
                 const float* __restrict__ Vh,
                 const int*   __restrict__ kv_mask,
                 float* __restrict__ Out)   // [B, L, D]
{
    __shared__ float Ks[64][64];
    __shared__ float Vs[64][64];
    __shared__ int   Ms[64];

    const int tid = threadIdx.x;
    const int bh  = blockIdx.y;          // b*H + h
    const int b   = bh >> 4;
    const int h   = bh & 15;
    const int q   = blockIdx.x * 128 + tid;

    // load query row into registers, fold in softmax scale
    float qr[HEAD_DIM];
    {
        const float* qp = Qh + ((size_t)bh * SEQ + q) * HEAD_DIM;
#pragma unroll
        for (int d4 = 0; d4 < 16; ++d4) {
            float4 v = *(const float4*)&qp[d4 * 4];
            qr[d4 * 4 + 0] = v.x * QK_SCALE;
            qr[d4 * 4 + 1] = v.y * QK_SCALE;
            qr[d4 * 4 + 2] = v.z * QK_SCALE;
            qr[d4 * 4 + 3] = v.w * QK_SCALE;
        }
    }

    float Oacc[HEAD_DIM];
#pragma unroll
    for (int d = 0; d < HEAD_DIM; ++d) Oacc[d] = 0.0f;
    float mrun = -3.0e38f;
    float lrun = 0.0f;

    const float* Kbase = Kh + (size_t)bh * SEQ * HEAD_DIM;
    const float* Vbase = Vh + (size_t)bh * SEQ * HEAD_DIM;
    const int*   Mbase = kv_mask + b * SEQ;

    for (int j0 = 0; j0 < SEQ; j0 += 64) {
        __syncthreads();
        // cooperative load of 64x64 K and V tiles (1024 float4 each)
        for (int f = tid; f < 1024; f += 128) {
            const int r  = f >> 4;
            const int c  = (f & 15) << 2;
            *(float4*)&Ks[r][c] = *(const float4*)&Kbase[(size_t)(j0 + r) * HEAD_DIM + c];
            *(float4*)&Vs[r][c] = *(const float4*)&Vbase[(size_t)(j0 + r) * HEAD_DIM + c];
        }
        if (tid < 64) Ms[tid] = Mbase[j0 + tid];
        __syncthreads();

        // process this 64-key tile in 16-key register chunks
#pragma unroll
        for (int c0 = 0; c0 < 64; c0 += 16) {
            float s[16];
            float cmax = -3.0e38f;
#pragma unroll
            for (int jj = 0; jj < 16; ++jj) {
                const int j = c0 + jj;
                float a = 0.0f;
#pragma unroll
                for (int d4 = 0; d4 < 16; ++d4) {
                    float4 kv = *(float4*)&Ks[j][d4 * 4];
                    a = fmaf(qr[d4 * 4 + 0], kv.x, a);
                    a = fmaf(qr[d4 * 4 + 1], kv.y, a);
                    a = fmaf(qr[d4 * 4 + 2], kv.z, a);
                    a = fmaf(qr[d4 * 4 + 3], kv.w, a);
                }
                s[jj] = Ms[j] ? a : -3.0e38f;
                cmax = fmaxf(cmax, s[jj]);
            }
            const float nm = fmaxf(mrun, cmax);
            const float fct = __expf(mrun - nm);
            mrun = nm;
            lrun *= fct;
#pragma unroll
            for (int d = 0; d < HEAD_DIM; ++d) Oacc[d] *= fct;
#pragma unroll
            for (int jj = 0; jj < 16; ++jj) {
                const float p = __expf(s[jj] - mrun);
                lrun += p;
                const int j = c0 + jj;
#pragma unroll
                for (int d4 = 0; d4 < 16; ++d4) {
                    float4 vv = *(float4*)&Vs[j][d4 * 4];
                    Oacc[d4 * 4 + 0] = fmaf(p, vv.x, Oacc[d4 * 4 + 0]);
                    Oacc[d4 * 4 + 1] = fmaf(p, vv.y, Oacc[d4 * 4 + 1]);
                    Oacc[d4 * 4 + 2] = fmaf(p, vv.z, Oacc[d4 * 4 + 2]);
                    Oacc[d4 * 4 + 3] = fmaf(p, vv.w, Oacc[d4 * 4 + 3]);
                }
            }
        }
    }

    const float inv = 1.0f / lrun;
    float* dst = Out + ((size_t)b * SEQ + q) * DIMN + h * HEAD_DIM;
#pragma unroll
    for (int d4 = 0; d4 < 16; ++d4) {
        float4 r;
        r.x = Oacc[d4 * 4 + 0] * inv;
        r.y = Oacc[d4 * 4 + 1] * inv;
        r.z = Oacc[d4 * 4 + 2] * inv;
        r.w = Oacc[d4 * 4 + 3] * inv;
        *(float4*)&dst[d4 * 4] = r;
    }
}

// ---------------------------------------------------------------------------
extern "C" void kernel_launch(void* const* d_in, const int* in_sizes, int n_in,
                              void* d_out, int out_size)
{
    const float* q    = (const float*)d_in[0];
    const float* k    = (const float*)d_in[1];
    const float* v    = (const float*)d_in[2];
    const int*   mask = (const int*)  d_in[3];
    const float* Wq   = (const float*)d_in[4];
    const float* bq   = (const float*)d_in[5];
    const float* Wk   = (const float*)d_in[6];
    const float* bk   = (const float*)d_in[7];
    const float* Wv   = (const float*)d_in[8];
    const float* bv   = (const float*)d_in[9];
    const float* Wo   = (const float*)d_in[10];
    const float* bo   = (const float*)d_in[11];
    float*       out  = (float*)d_out;

    void *p_qh = nullptr, *p_kh = nullptr, *p_vh = nullptr, *p_attn = nullptr;
    cudaGetSymbolAddress(&p_qh,   g_qh);
    cudaGetSymbolAddress(&p_kh,   g_kh);
    cudaGetSymbolAddress(&p_vh,   g_vh);
    cudaGetSymbolAddress(&p_attn, g_attn);

    dim3 gg(DIMN / BN, MROWS / BM);   // (8, 32)
    dim3 gb(256);

    gemm_bias_kernel<<<gg, gb>>>(q, Wq, bq, (float*)p_qh, MROWS, DIMN, DIMN, 0);
    gemm_bias_kernel<<<gg, gb>>>(k, Wk, bk, (float*)p_kh, MROWS, DIMN, DIMN, 0);
    gemm_bias_kernel<<<gg, gb>>>(v, Wv, bv, (float*)p_vh, MROWS, DIMN, DIMN, 0);

    dim3 ag(SEQ / 128, BATCH * NUM_HEADS);   // (16, 32)
    attn_kernel<<<ag, 128>>>((const float*)p_qh, (const float*)p_kh,
                             (const float*)p_vh, mask, (float*)p_attn);

    gemm_bias_kernel<<<gg, gb>>>((const float*)p_attn, Wo, bo, out,
                                 MROWS, DIMN, DIMN, 1);
}

// round 6
// speedup vs baseline: 4.9375x; 4.9375x over previous
#include <cuda_runtime.h>
#include <cuda_bf16.h>
#include <cuda_fp16.h>
#include <stdint.h>

// Problem constants
#define DIMN      1024
#define NUM_HEADS 16
#define HEAD_DIM  64
#define BATCH     2
#define SEQ       2048
#define MROWS     (BATCH * SEQ)          // 4096
#define QK_SCALE  0.125f                 // 64^-0.5

// ---------------- scratch (static device globals; no allocation) -----------
__device__ float g_qh[BATCH * NUM_HEADS * SEQ * HEAD_DIM];   // [B,H,L,hd]
__device__ float g_kh[BATCH * NUM_HEADS * SEQ * HEAD_DIM];
__device__ float g_vh[BATCH * NUM_HEADS * SEQ * HEAD_DIM];
__device__ float g_attn[BATCH * SEQ * DIMN];                 // [B,L,D]

// ---------------------------------------------------------------------------
// small PTX helpers
// ---------------------------------------------------------------------------
__device__ __forceinline__ uint32_t smem_cast(const void* p) {
    return (uint32_t)__cvta_generic_to_shared(p);
}
__device__ __forceinline__ void ldsm4(uint32_t& d0, uint32_t& d1, uint32_t& d2,
                                      uint32_t& d3, uint32_t a) {
    asm volatile("ldmatrix.sync.aligned.m8n8.x4.shared.b16 {%0,%1,%2,%3},[%4];"
                 : "=r"(d0), "=r"(d1), "=r"(d2), "=r"(d3) : "r"(a));
}
__device__ __forceinline__ void ldsm4t(uint32_t& d0, uint32_t& d1, uint32_t& d2,
                                       uint32_t& d3, uint32_t a) {
    asm volatile("ldmatrix.sync.aligned.m8n8.x4.trans.shared.b16 {%0,%1,%2,%3},[%4];"
                 : "=r"(d0), "=r"(d1), "=r"(d2), "=r"(d3) : "r"(a));
}
__device__ __forceinline__ void mma_bf16(float* c, const uint32_t* a,
                                         uint32_t b0, uint32_t b1) {
    asm volatile(
        "mma.sync.aligned.m16n8k16.row.col.f32.bf16.bf16.f32 "
        "{%0,%1,%2,%3},{%4,%5,%6,%7},{%8,%9},{%0,%1,%2,%3};"
        : "+f"(c[0]), "+f"(c[1]), "+f"(c[2]), "+f"(c[3])
        : "r"(a[0]), "r"(a[1]), "r"(a[2]), "r"(a[3]), "r"(b0), "r"(b1));
}
__device__ __forceinline__ void mma_f16(float* c, const uint32_t* a,
                                        uint32_t b0, uint32_t b1) {
    asm volatile(
        "mma.sync.aligned.m16n8k16.row.col.f32.f16.f16.f32 "
        "{%0,%1,%2,%3},{%4,%5,%6,%7},{%8,%9},{%0,%1,%2,%3};"
        : "+f"(c[0]), "+f"(c[1]), "+f"(c[2]), "+f"(c[3])
        : "r"(a[0]), "r"(a[1]), "r"(a[2]), "r"(a[3]), "r"(b0), "r"(b1));
}
__device__ __forceinline__ uint32_t h2pack(float x, float y) {
    __half2 t = __floats2half2_rn(x, y);
    return *reinterpret_cast<uint32_t*>(&t);
}
// split a float pair into bf16 hi/lo and store packed
__device__ __forceinline__ void split_store(float x, float y,
                                            __nv_bfloat16* ph, __nv_bfloat16* pl) {
    __nv_bfloat16 hx = __float2bfloat16(x);
    __nv_bfloat16 hy = __float2bfloat16(y);
    __nv_bfloat16 lx = __float2bfloat16(x - __bfloat162float(hx));
    __nv_bfloat16 ly = __float2bfloat16(y - __bfloat162float(hy));
    __nv_bfloat162 h; h.x = hx; h.y = hy;
    __nv_bfloat162 l; l.x = lx; l.y = ly;
    *reinterpret_cast<__nv_bfloat162*>(ph) = h;
    *reinterpret_cast<__nv_bfloat162*>(pl) = l;
}

// ---------------------------------------------------------------------------
// Split-bf16 tensor-core GEMM:  C = A[M,K] @ W[N,K]^T + bias
// BM=BN=128, BK=32, 256 threads (8 warps as 4m x 2n, warp tile 32x64).
// A = A_hi + A_lo (bf16 each); C = Ah@Bh + Ah@Bl + Al@Bh  (~fp32 accurate).
// mode 0: head-split store [B,H,L,hd]; mode 1: flat [M,N].
// ---------------------------------------------------------------------------
#define GBK  32
#define GSTR 40    // smem row stride in bf16 (80B = 5x16B -> ldmatrix conflict-free)

__global__ __launch_bounds__(256, 2)
void gemm_split_kernel(const float* __restrict__ A, const float* __restrict__ W,
                       const float* __restrict__ bias, float* __restrict__ C,
                       int mode)
{
    __shared__ __nv_bfloat16 sAh[128 * GSTR];
    __shared__ __nv_bfloat16 sAl[128 * GSTR];
    __shared__ __nv_bfloat16 sBh[128 * GSTR];
    __shared__ __nv_bfloat16 sBl[128 * GSTR];

    const int tid  = threadIdx.x;
    const int lane = tid & 31;
    const int wid  = tid >> 5;
    const int wm   = wid & 3;        // 4 warps in m
    const int wn   = wid >> 2;       // 2 warps in n
    const int m0   = blockIdx.y * 128;
    const int n0   = blockIdx.x * 128;

    // cooperative load: thread covers row = tid>>1, 16 consecutive floats
    const int lr = tid >> 1;
    const int lc = (tid & 1) << 4;

    const float* Ag = A + (size_t)(m0 + lr) * DIMN + lc;
    const float* Wg = W + (size_t)(n0 + lr) * DIMN + lc;
    __nv_bfloat16* pAh = &sAh[lr * GSTR + lc];
    __nv_bfloat16* pAl = &sAl[lr * GSTR + lc];
    __nv_bfloat16* pBh = &sBh[lr * GSTR + lc];
    __nv_bfloat16* pBl = &sBl[lr * GSTR + lc];

    float acc[2][8][4];
#pragma unroll
    for (int i = 0; i < 2; ++i)
#pragma unroll
        for (int j = 0; j < 8; ++j)
#pragma unroll
            for (int r = 0; r < 4; ++r) acc[i][j][r] = 0.0f;

    // ldmatrix addresses
    const uint32_t aAh = smem_cast(sAh), aAl = smem_cast(sAl);
    const uint32_t aBh = smem_cast(sBh), aBl = smem_cast(sBl);
    const int arow = wm * 32 + (lane & 15);
    const uint32_t aoff0 = (uint32_t)((arow)      * GSTR + (lane >> 4) * 8) * 2;
    const uint32_t aoff1 = (uint32_t)((arow + 16) * GSTR + (lane >> 4) * 8) * 2;
    const int bn = wn * 64 + ((lane >> 4) << 3) + (lane & 7);
    const uint32_t boff = (uint32_t)(bn * GSTR + ((lane >> 3) & 1) * 8) * 2;

    for (int kt = 0; kt < DIMN; kt += GBK) {
        float4 va[4], vw[4];
#pragma unroll
        for (int i = 0; i < 4; ++i) {
            va[i] = *(const float4*)(Ag + kt + 4 * i);
            vw[i] = *(const float4*)(Wg + kt + 4 * i);
        }
        __syncthreads();
#pragma unroll
        for (int i = 0; i < 4; ++i) {
            split_store(va[i].x, va[i].y, pAh + 4 * i,     pAl + 4 * i);
            split_store(va[i].z, va[i].w, pAh + 4 * i + 2, pAl + 4 * i + 2);
            split_store(vw[i].x, vw[i].y, pBh + 4 * i,     pBl + 4 * i);
            split_store(vw[i].z, vw[i].w, pBh + 4 * i + 2, pBl + 4 * i + 2);
        }
        __syncthreads();

#pragma unroll
        for (int ks = 0; ks < 2; ++ks) {
            uint32_t ah0[4], ah1[4], al0[4], al1[4];
            ldsm4(ah0[0], ah0[1], ah0[2], ah0[3], aAh + aoff0 + ks * 32);
            ldsm4(ah1[0], ah1[1], ah1[2], ah1[3], aAh + aoff1 + ks * 32);
            ldsm4(al0[0], al0[1], al0[2], al0[3], aAl + aoff0 + ks * 32);
            ldsm4(al1[0], al1[1], al1[2], al1[3], aAl + aoff1 + ks * 32);
#pragma unroll
            for (int p = 0; p < 4; ++p) {
                uint32_t bh[4], bl[4];
                const uint32_t po = (uint32_t)(p * 16 * GSTR * 2 + ks * 32);
                ldsm4(bh[0], bh[1], bh[2], bh[3], aBh + boff + po);
                ldsm4(bl[0], bl[1], bl[2], bl[3], aBl + boff + po);
                // ntile 2p : b-regs bh[0],bh[1] / bl[0],bl[1]
                mma_bf16(acc[0][2 * p],     ah0, bh[0], bh[1]);
                mma_bf16(acc[1][2 * p],     ah1, bh[0], bh[1]);
                mma_bf16(acc[0][2 * p],     ah0, bl[0], bl[1]);
                mma_bf16(acc[1][2 * p],     ah1, bl[0], bl[1]);
                mma_bf16(acc[0][2 * p],     al0, bh[0], bh[1]);
                mma_bf16(acc[1][2 * p],     al1, bh[0], bh[1]);
                // ntile 2p+1
                mma_bf16(acc[0][2 * p + 1], ah0, bh[2], bh[3]);
                mma_bf16(acc[1][2 * p + 1], ah1, bh[2], bh[3]);
                mma_bf16(acc[0][2 * p + 1], ah0, bl[2], bl[3]);
                mma_bf16(acc[1][2 * p + 1], ah1, bl[2], bl[3]);
                mma_bf16(acc[0][2 * p + 1], al0, bh[2], bh[3]);
                mma_bf16(acc[1][2 * p + 1], al1, bh[2], bh[3]);
            }
        }
    }

    // epilogue: bias + store
#pragma unroll
    for (int mt = 0; mt < 2; ++mt) {
#pragma unroll
        for (int nt = 0; nt < 8; ++nt) {
            const int r = m0 + wm * 32 + mt * 16 + (lane >> 2);
            const int c = n0 + wn * 64 + nt * 8 + ((lane & 3) << 1);
            const float2 bv = *(const float2*)&bias[c];
            float2 o0, o1;
            o0.x = acc[mt][nt][0] + bv.x;  o0.y = acc[mt][nt][1] + bv.y;
            o1.x = acc[mt][nt][2] + bv.x;  o1.y = acc[mt][nt][3] + bv.y;
            if (mode == 1) {
                *(float2*)&C[(size_t)r * DIMN + c]       = o0;
                *(float2*)&C[(size_t)(r + 8) * DIMN + c] = o1;
            } else {
                const int h = c >> 6, hd = c & 63;
                {
                    const int b = r >> 11, l = r & 2047;
                    size_t d = ((((size_t)b * NUM_HEADS + h) * SEQ + l) * HEAD_DIM + hd);
                    *(float2*)&C[d] = o0;
                }
                {
                    const int r2 = r + 8;
                    const int b = r2 >> 11, l = r2 & 2047;
                    size_t d = ((((size_t)b * NUM_HEADS + h) * SEQ + l) * HEAD_DIM + hd);
                    *(float2*)&C[d] = o1;
                }
            }
        }
    }
}

// ---------------------------------------------------------------------------
// Tensor-core flash attention (fp16 MMA, fp32 accum, online softmax in regs).
// grid (SEQ/128, B*H), 256 threads (8 warps, 16 queries each).
// K/V tiles of 64 keys staged fp32->fp16 in SMEM; QK C-frags convert directly
// into PV A-frags.
// ---------------------------------------------------------------------------
#define ASTR 72    // fp16 smem row stride (144B = 9x16B -> ldmatrix conflict-free)

__global__ __launch_bounds__(256, 2)
void attn_mma_kernel(const float* __restrict__ Qh, const float* __restrict__ Kh,
                     const float* __restrict__ Vh, const int* __restrict__ kv_mask,
                     float* __restrict__ Out)
{
    __shared__ __half sK[64 * ASTR];
    __shared__ __half sV[64 * ASTR];
    __shared__ float  sM[64];

    const int tid  = threadIdx.x;
    const int lane = tid & 31;
    const int wid  = tid >> 5;
    const int bh   = blockIdx.y;
    const int b    = bh >> 4;
    const int h    = bh & 15;
    const int q0   = blockIdx.x * 128 + wid * 16;   // warp's first query

    // ---- Q fragments (pre-scaled), loaded straight from global fp32 ----
    uint32_t aq[4][4];
    {
        const float* Qbase = Qh + (size_t)bh * SEQ * HEAD_DIM;
#pragma unroll
        for (int ks = 0; ks < 4; ++ks)
#pragma unroll
            for (int j = 0; j < 4; ++j) {
                const int r = q0 + (lane >> 2) + (j & 1) * 8;
                const int c = ks * 16 + ((j >> 1) << 3) + ((lane & 3) << 1);
                const float2 v = *(const float2*)&Qbase[(size_t)r * HEAD_DIM + c];
                aq[ks][j] = h2pack(v.x * QK_SCALE, v.y * QK_SCALE);
            }
    }

    float O[8][4];
#pragma unroll
    for (int i = 0; i < 8; ++i)
#pragma unroll
        for (int j = 0; j < 4; ++j) O[i][j] = 0.0f;
    float m0r = -1e30f, m1r = -1e30f, l0r = 0.0f, l1r = 0.0f;

    const float* Kb = Kh + (size_t)bh * SEQ * HEAD_DIM;
    const float* Vb = Vh + (size_t)bh * SEQ * HEAD_DIM;
    const int*   Mb = kv_mask + b * SEQ;

    const uint32_t aK = smem_cast(sK), aV = smem_cast(sV);
    // QK B-frag base: key = ((lane>>4)<<3)+(lane&7), chunk = (lane>>3)&1
    const uint32_t kfrag =
        (uint32_t)(((((lane >> 4) << 3) + (lane & 7)) * ASTR + ((lane >> 3) & 1) * 8)) * 2;
    // PV (trans) B-frag base: key = ((lane>>3)&1)*8 + (lane&7), chunk = lane>>4
    const uint32_t vfrag =
        (uint32_t)((((((lane >> 3) & 1) << 3) + (lane & 7)) * ASTR + (lane >> 4) * 8)) * 2;

    const int rrow = tid >> 2;          // 0..63
    const int rc   = (tid & 3) << 4;    // 0,16,32,48

    for (int j0 = 0; j0 < SEQ; j0 += 64) {
        // stage K/V tile fp32 -> fp16
        float4 kv4[4], vv4[4];
#pragma unroll
        for (int i = 0; i < 4; ++i) {
            kv4[i] = *(const float4*)(Kb + (size_t)(j0 + rrow) * HEAD_DIM + rc + 4 * i);
            vv4[i] = *(const float4*)(Vb + (size_t)(j0 + rrow) * HEAD_DIM + rc + 4 * i);
        }
        __syncthreads();
#pragma unroll
        for (int i = 0; i < 4; ++i) {
            *(__half2*)&sK[rrow * ASTR + rc + 4 * i]     = __floats2half2_rn(kv4[i].x, kv4[i].y);
            *(__half2*)&sK[rrow * ASTR + rc + 4 * i + 2] = __floats2half2_rn(kv4[i].z, kv4[i].w);
            *(__half2*)&sV[rrow * ASTR + rc + 4 * i]     = __floats2half2_rn(vv4[i].x, vv4[i].y);
            *(__half2*)&sV[rrow * ASTR + rc + 4 * i + 2] = __floats2half2_rn(vv4[i].z, vv4[i].w);
        }
        if (tid < 64) sM[tid] = Mb[j0 + tid] ? 0.0f : -1e30f;
        __syncthreads();

        // ---- scores S = Q @ K^T ----
        float S[8][4];
#pragma unroll
        for (int i = 0; i < 8; ++i)
#pragma unroll
            for (int j = 0; j < 4; ++j) S[i][j] = 0.0f;
#pragma unroll
        for (int ks = 0; ks < 4; ++ks) {
#pragma unroll
            for (int p = 0; p < 4; ++p) {
                uint32_t bq[4];
                ldsm4(bq[0], bq[1], bq[2], bq[3],
                      aK + kfrag + (uint32_t)(p * 16 * ASTR * 2 + ks * 32));
                mma_f16(S[2 * p],     aq[ks], bq[0], bq[1]);
                mma_f16(S[2 * p + 1], aq[ks], bq[2], bq[3]);
            }
        }

        // ---- mask + row max ----
        float mx0 = -1e30f, mx1 = -1e30f;
#pragma unroll
        for (int nt = 0; nt < 8; ++nt) {
            const int kk = nt * 8 + ((lane & 3) << 1);
            const float2 md = *(const float2*)&sM[kk];
            S[nt][0] += md.x; S[nt][1] += md.y;
            S[nt][2] += md.x; S[nt][3] += md.y;
            mx0 = fmaxf(mx0, fmaxf(S[nt][0], S[nt][1]));
            mx1 = fmaxf(mx1, fmaxf(S[nt][2], S[nt][3]));
        }
        mx0 = fmaxf(mx0, __shfl_xor_sync(0xffffffffu, mx0, 1));
        mx0 = fmaxf(mx0, __shfl_xor_sync(0xffffffffu, mx0, 2));
        mx1 = fmaxf(mx1, __shfl_xor_sync(0xffffffffu, mx1, 1));
        mx1 = fmaxf(mx1, __shfl_xor_sync(0xffffffffu, mx1, 2));

        const float nm0 = fmaxf(m0r, mx0), nm1 = fmaxf(m1r, mx1);
        const float f0 = __expf(m0r - nm0), f1 = __expf(m1r - nm1);
        m0r = nm0; m1r = nm1;

        // ---- exponentiate; accumulate row sums ----
        float s0 = 0.0f, s1 = 0.0f;
#pragma unroll
        for (int nt = 0; nt < 8; ++nt) {
            S[nt][0] = __expf(S[nt][0] - nm0);
            S[nt][1] = __expf(S[nt][1] - nm0);
            S[nt][2] = __expf(S[nt][2] - nm1);
            S[nt][3] = __expf(S[nt][3] - nm1);
            s0 += S[nt][0] + S[nt][1];
            s1 += S[nt][2] + S[nt][3];
        }
        s0 += __shfl_xor_sync(0xffffffffu, s0, 1);
        s0 += __shfl_xor_sync(0xffffffffu, s0, 2);
        s1 += __shfl_xor_sync(0xffffffffu, s1, 1);
        s1 += __shfl_xor_sync(0xffffffffu, s1, 2);
        l0r = l0r * f0 + s0;
        l1r = l1r * f1 + s1;

        // rescale O
#pragma unroll
        for (int nt = 0; nt < 8; ++nt) {
            O[nt][0] *= f0; O[nt][1] *= f0;
            O[nt][2] *= f1; O[nt][3] *= f1;
        }

        // ---- O += P @ V ----
#pragma unroll
        for (int ks = 0; ks < 4; ++ks) {
            uint32_t pa[4];
            pa[0] = h2pack(S[2 * ks][0],     S[2 * ks][1]);
            pa[1] = h2pack(S[2 * ks][2],     S[2 * ks][3]);
            pa[2] = h2pack(S[2 * ks + 1][0], S[2 * ks + 1][1]);
            pa[3] = h2pack(S[2 * ks + 1][2], S[2 * ks + 1][3]);
#pragma unroll
            for (int p = 0; p < 4; ++p) {
                uint32_t bv[4];
                ldsm4t(bv[0], bv[1], bv[2], bv[3],
                       aV + vfrag + (uint32_t)(ks * 16 * ASTR * 2 + p * 32));
                mma_f16(O[2 * p],     pa, bv[0], bv[1]);
                mma_f16(O[2 * p + 1], pa, bv[2], bv[3]);
            }
        }
    }

    // ---- normalize + store to [B,L,D] ----
    const float inv0 = 1.0f / l0r, inv1 = 1.0f / l1r;
    const int qr = q0 + (lane >> 2);
    float* d0 = Out + ((size_t)b * SEQ + qr) * DIMN + h * HEAD_DIM;
    float* d1 = Out + ((size_t)b * SEQ + qr + 8) * DIMN + h * HEAD_DIM;
#pragma unroll
    for (int nt = 0; nt < 8; ++nt) {
        const int c = nt * 8 + ((lane & 3) << 1);
        float2 o0, o1;
        o0.x = O[nt][0] * inv0;  o0.y = O[nt][1] * inv0;
        o1.x = O[nt][2] * inv1;  o1.y = O[nt][3] * inv1;
        *(float2*)&d0[c] = o0;
        *(float2*)&d1[c] = o1;
    }
}

// ---------------------------------------------------------------------------
extern "C" void kernel_launch(void* const* d_in, const int* in_sizes, int n_in,
                              void* d_out, int out_size)
{
    const float* q    = (const float*)d_in[0];
    const float* k    = (const float*)d_in[1];
    const float* v    = (const float*)d_in[2];
    const int*   mask = (const int*)  d_in[3];
    const float* Wq   = (const float*)d_in[4];
    const float* bq   = (const float*)d_in[5];
    const float* Wk   = (const float*)d_in[6];
    const float* bk   = (const float*)d_in[7];
    const float* Wv   = (const float*)d_in[8];
    const float* bv   = (const float*)d_in[9];
    const float* Wo   = (const float*)d_in[10];
    const float* bo   = (const float*)d_in[11];
    float*       out  = (float*)d_out;

    void *p_qh = nullptr, *p_kh = nullptr, *p_vh = nullptr, *p_attn = nullptr;
    cudaGetSymbolAddress(&p_qh,   g_qh);
    cudaGetSymbolAddress(&p_kh,   g_kh);
    cudaGetSymbolAddress(&p_vh,   g_vh);
    cudaGetSymbolAddress(&p_attn, g_attn);

    dim3 gg(DIMN / 128, MROWS / 128);   // (8, 32)
    gemm_split_kernel<<<gg, 256>>>(q, Wq, bq, (float*)p_qh, 0);
    gemm_split_kernel<<<gg, 256>>>(k, Wk, bk, (float*)p_kh, 0);
    gemm_split_kernel<<<gg, 256>>>(v, Wv, bv, (float*)p_vh, 0);

    dim3 ag(SEQ / 128, BATCH * NUM_HEADS);   // (16, 32)
    attn_mma_kernel<<<ag, 256>>>((const float*)p_qh, (const float*)p_kh,
                                 (const float*)p_vh, mask, (float*)p_attn);

    gemm_split_kernel<<<gg, 256>>>((const float*)p_attn, Wo, bo, out, 1);
}

// round 7
// speedup vs baseline: 6.2579x; 1.2674x over previous
#include <cuda_runtime.h>
#include <cuda_bf16.h>
#include <cuda_fp16.h>
#include <stdint.h>

// Problem constants
#define DIMN      1024
#define NUM_HEADS 16
#define HEAD_DIM  64
#define BATCH     2
#define SEQ       2048
#define MROWS     (BATCH * SEQ)          // 4096
#define NELEM     (MROWS * DIMN)         // 4,194,304
#define WELEM     (DIMN * DIMN)          // 1,048,576
#define QK_SCALE  0.125f

// ---------------- scratch (static device globals; no allocation) -----------
__device__ __nv_bfloat16 g_xh[3 * NELEM];   // split hi of q,k,v inputs
__device__ __nv_bfloat16 g_xl[3 * NELEM];   // split lo
__device__ __nv_bfloat16 g_wh[4 * WELEM];   // split hi of Wq,Wk,Wv,Wo
__device__ __nv_bfloat16 g_wl[4 * WELEM];
__device__ __half        g_q16[NELEM];      // fp16 [B,H,L,hd], pre-scaled
__device__ __half        g_k16[NELEM];
__device__ __half        g_v16[NELEM];
__device__ __nv_bfloat16 g_ah[NELEM];       // attn output split hi [B,L,D]
__device__ __nv_bfloat16 g_al[NELEM];       // attn output split lo

// ---------------------------------------------------------------------------
// PTX helpers
// ---------------------------------------------------------------------------
__device__ __forceinline__ uint32_t smem_cast(const void* p) {
    return (uint32_t)__cvta_generic_to_shared(p);
}
__device__ __forceinline__ void cp16(uint32_t s, const void* g) {
    asm volatile("cp.async.cg.shared.global [%0], [%1], 16;" :: "r"(s), "l"(g));
}
__device__ __forceinline__ void cp_commit() {
    asm volatile("cp.async.commit_group;");
}
template <int N>
__device__ __forceinline__ void cp_wait() {
    asm volatile("cp.async.wait_group %0;" :: "n"(N));
}
__device__ __forceinline__ void ldsm4(uint32_t& d0, uint32_t& d1, uint32_t& d2,
                                      uint32_t& d3, uint32_t a) {
    asm volatile("ldmatrix.sync.aligned.m8n8.x4.shared.b16 {%0,%1,%2,%3},[%4];"
                 : "=r"(d0), "=r"(d1), "=r"(d2), "=r"(d3) : "r"(a));
}
__device__ __forceinline__ void ldsm4t(uint32_t& d0, uint32_t& d1, uint32_t& d2,
                                       uint32_t& d3, uint32_t a) {
    asm volatile("ldmatrix.sync.aligned.m8n8.x4.trans.shared.b16 {%0,%1,%2,%3},[%4];"
                 : "=r"(d0), "=r"(d1), "=r"(d2), "=r"(d3) : "r"(a));
}
__device__ __forceinline__ void mma_bf16(float* c, const uint32_t* a,
                                         uint32_t b0, uint32_t b1) {
    asm volatile(
        "mma.sync.aligned.m16n8k16.row.col.f32.bf16.bf16.f32 "
        "{%0,%1,%2,%3},{%4,%5,%6,%7},{%8,%9},{%0,%1,%2,%3};"
        : "+f"(c[0]), "+f"(c[1]), "+f"(c[2]), "+f"(c[3])
        : "r"(a[0]), "r"(a[1]), "r"(a[2]), "r"(a[3]), "r"(b0), "r"(b1));
}
__device__ __forceinline__ void mma_f16(float* c, const uint32_t* a,
                                        uint32_t b0, uint32_t b1) {
    asm volatile(
        "mma.sync.aligned.m16n8k16.row.col.f32.f16.f16.f32 "
        "{%0,%1,%2,%3},{%4,%5,%6,%7},{%8,%9},{%0,%1,%2,%3};"
        : "+f"(c[0]), "+f"(c[1]), "+f"(c[2]), "+f"(c[3])
        : "r"(a[0]), "r"(a[1]), "r"(a[2]), "r"(a[3]), "r"(b0), "r"(b1));
}
__device__ __forceinline__ void split2(float x, float y,
                                       __nv_bfloat162& hi, __nv_bfloat162& lo) {
    __nv_bfloat16 hx = __float2bfloat16(x);
    __nv_bfloat16 hy = __float2bfloat16(y);
    hi.x = hx; hi.y = hy;
    lo.x = __float2bfloat16(x - __bfloat162float(hx));
    lo.y = __float2bfloat16(y - __bfloat162float(hy));
}

// ---------------------------------------------------------------------------
// Split kernel: fp32 -> bf16 hi/lo, up to 4 tensors selected by blockIdx.y.
// Each thread converts 4 elements (float4 load, uint2 stores).
// ---------------------------------------------------------------------------
__global__ __launch_bounds__(256)
void split_kernel(const float* __restrict__ S0, const float* __restrict__ S1,
                  const float* __restrict__ S2, const float* __restrict__ S3,
                  __nv_bfloat16* __restrict__ H, __nv_bfloat16* __restrict__ L,
                  int n_per)
{
    const int t = blockIdx.y;
    const float* S = (t == 0) ? S0 : (t == 1) ? S1 : (t == 2) ? S2 : S3;
    const int i = (blockIdx.x * 256 + threadIdx.x) * 4;
    if (i >= n_per) return;
    const size_t base = (size_t)t * n_per + i;
    float4 v = *(const float4*)(S + i);
    __nv_bfloat162 h0, l0, h1, l1;
    split2(v.x, v.y, h0, l0);
    split2(v.z, v.w, h1, l1);
    uint2 hp, lp;
    hp.x = *(uint32_t*)&h0; hp.y = *(uint32_t*)&h1;
    lp.x = *(uint32_t*)&l0; lp.y = *(uint32_t*)&l1;
    *(uint2*)(H + base) = hp;
    *(uint2*)(L + base) = lp;
}

// ---------------------------------------------------------------------------
// Split-bf16 tensor-core GEMM, presplit inputs, cp.async 4-stage pipeline.
// C = (Ah+Al)[M,K] @ (Wh+Wl)[N,K]^T + bias   (drop Al@Wl term)
// BM=BN=128, BK=16, 256 threads (8 warps 4m x 2n, warp tile 32x64).
// mode 0: C fp16 head-split [B,H,L,hd], scaled.   mode 1: C fp32 flat [M,N].
// ---------------------------------------------------------------------------
#define GBK        16
#define GSTR2      24                         // smem row stride (48B, ldmatrix-clean)
#define G_STAGES   4
#define G_MAT_ELE  (128 * GSTR2)              // 3072 bf16 per matrix tile
#define G_STAGE_B  (4 * G_MAT_ELE * 2)        // 24576 bytes per stage
#define G_SMEM     (G_STAGES * G_STAGE_B)     // 98304 bytes

__global__ __launch_bounds__(256, 2)
void gemm_ts_kernel(const __nv_bfloat16* __restrict__ Ah,
                    const __nv_bfloat16* __restrict__ Al,
                    const __nv_bfloat16* __restrict__ Wh,
                    const __nv_bfloat16* __restrict__ Wl,
                    const float* __restrict__ bias,
                    __half* __restrict__ Ch, float* __restrict__ Cf,
                    float scale, int mode)
{
    extern __shared__ __nv_bfloat16 sg[];
    const int tid  = threadIdx.x;
    const int lane = tid & 31;
    const int wid  = tid >> 5;
    const int wm   = wid & 3;
    const int wn   = wid >> 2;
    const int m0   = blockIdx.y * 128;
    const int n0   = blockIdx.x * 128;

    const uint32_t sbase = smem_cast(sg);

    // cp.async mapping: row = tid>>1, chunk = tid&1 (16 bf16/row = 2 chunks)
    const int r   = tid >> 1;
    const int ccp = tid & 1;
    const __nv_bfloat16* gAh = Ah + (size_t)(m0 + r) * DIMN + ccp * 8;
    const __nv_bfloat16* gAl = Al + (size_t)(m0 + r) * DIMN + ccp * 8;
    const __nv_bfloat16* gWh = Wh + (size_t)(n0 + r) * DIMN + ccp * 8;
    const __nv_bfloat16* gWl = Wl + (size_t)(n0 + r) * DIMN + ccp * 8;
    const uint32_t soff = (uint32_t)(r * GSTR2 + ccp * 8) * 2;

    float acc[2][8][4];
#pragma unroll
    for (int i = 0; i < 2; ++i)
#pragma unroll
        for (int j = 0; j < 8; ++j)
#pragma unroll
            for (int q = 0; q < 4; ++q) acc[i][j][q] = 0.0f;

    // ldmatrix offsets (bytes, within one matrix tile)
    const int arow = wm * 32 + (lane & 15);
    const uint32_t aoff0 = (uint32_t)(arow * GSTR2 + (lane >> 4) * 8) * 2;
    const uint32_t aoff1 = aoff0 + (uint32_t)(16 * GSTR2) * 2;
    const int bn = wn * 64 + ((lane >> 4) << 3) + (lane & 7);
    const uint32_t boff = (uint32_t)(bn * GSTR2 + ((lane >> 3) & 1) * 8) * 2;

#define G_ISSUE(KT, ST)                                                     \
    do {                                                                    \
        uint32_t sb_ = sbase + (uint32_t)(ST) * G_STAGE_B;                  \
        cp16(sb_ + 0 * G_MAT_ELE * 2 + soff, gAh + (KT));                   \
        cp16(sb_ + 1 * G_MAT_ELE * 2 + soff, gAl + (KT));                   \
        cp16(sb_ + 2 * G_MAT_ELE * 2 + soff, gWh + (KT));                   \
        cp16(sb_ + 3 * G_MAT_ELE * 2 + soff, gWl + (KT));                   \
    } while (0)

    // prologue: stages 0..2
#pragma unroll
    for (int s = 0; s < 3; ++s) { G_ISSUE(s * GBK, s); cp_commit(); }

    for (int kt = 0; kt < DIMN / GBK; ++kt) {
        cp_wait<2>();
        __syncthreads();
        if (kt + 3 < DIMN / GBK) G_ISSUE((kt + 3) * GBK, (kt + 3) & 3);
        cp_commit();

        const uint32_t sb  = sbase + (uint32_t)(kt & 3) * G_STAGE_B;
        const uint32_t aAh = sb;
        const uint32_t aAl = sb + 1 * G_MAT_ELE * 2;
        const uint32_t aBh = sb + 2 * G_MAT_ELE * 2;
        const uint32_t aBl = sb + 3 * G_MAT_ELE * 2;

        uint32_t ah0[4], ah1[4], al0[4], al1[4];
        ldsm4(ah0[0], ah0[1], ah0[2], ah0[3], aAh + aoff0);
        ldsm4(ah1[0], ah1[1], ah1[2], ah1[3], aAh + aoff1);
        ldsm4(al0[0], al0[1], al0[2], al0[3], aAl + aoff0);
        ldsm4(al1[0], al1[1], al1[2], al1[3], aAl + aoff1);
#pragma unroll
        for (int p = 0; p < 4; ++p) {
            uint32_t bh[4], bl[4];
            const uint32_t po = (uint32_t)(p * 16 * GSTR2) * 2;
            ldsm4(bh[0], bh[1], bh[2], bh[3], aBh + boff + po);
            ldsm4(bl[0], bl[1], bl[2], bl[3], aBl + boff + po);
            mma_bf16(acc[0][2 * p],     ah0, bh[0], bh[1]);
            mma_bf16(acc[1][2 * p],     ah1, bh[0], bh[1]);
            mma_bf16(acc[0][2 * p],     ah0, bl[0], bl[1]);
            mma_bf16(acc[1][2 * p],     ah1, bl[0], bl[1]);
            mma_bf16(acc[0][2 * p],     al0, bh[0], bh[1]);
            mma_bf16(acc[1][2 * p],     al1, bh[0], bh[1]);
            mma_bf16(acc[0][2 * p + 1], ah0, bh[2], bh[3]);
            mma_bf16(acc[1][2 * p + 1], ah1, bh[2], bh[3]);
            mma_bf16(acc[0][2 * p + 1], ah0, bl[2], bl[3]);
            mma_bf16(acc[1][2 * p + 1], ah1, bl[2], bl[3]);
            mma_bf16(acc[0][2 * p + 1], al0, bh[2], bh[3]);
            mma_bf16(acc[1][2 * p + 1], al1, bh[2], bh[3]);
        }
    }
#undef G_ISSUE

    // epilogue
#pragma unroll
    for (int mt = 0; mt < 2; ++mt) {
#pragma unroll
        for (int nt = 0; nt < 8; ++nt) {
            const int rr = m0 + wm * 32 + mt * 16 + (lane >> 2);
            const int cc = n0 + wn * 64 + nt * 8 + ((lane & 3) << 1);
            const float2 bv = *(const float2*)&bias[cc];
            const float o00 = acc[mt][nt][0] + bv.x;
            const float o01 = acc[mt][nt][1] + bv.y;
            const float o10 = acc[mt][nt][2] + bv.x;
            const float o11 = acc[mt][nt][3] + bv.y;
            if (mode == 1) {
                float2 a = {o00, o01}, b = {o10, o11};
                *(float2*)&Cf[(size_t)rr * DIMN + cc]       = a;
                *(float2*)&Cf[(size_t)(rr + 8) * DIMN + cc] = b;
            } else {
                const int h = cc >> 6, hd = cc & 63;
                {
                    const int b = rr >> 11, l = rr & 2047;
                    size_t d = ((((size_t)b * NUM_HEADS + h) * SEQ + l) * HEAD_DIM + hd);
                    *(__half2*)&Ch[d] = __floats2half2_rn(o00 * scale, o01 * scale);
                }
                {
                    const int r2 = rr + 8;
                    const int b = r2 >> 11, l = r2 & 2047;
                    size_t d = ((((size_t)b * NUM_HEADS + h) * SEQ + l) * HEAD_DIM + hd);
                    *(__half2*)&Ch[d] = __floats2half2_rn(o10 * scale, o11 * scale);
                }
            }
        }
    }
}

// ---------------------------------------------------------------------------
// Tensor-core flash attention: fp16 Q/K/V in global, cp.async 3-stage pipe.
// grid (SEQ/128, B*H), 256 threads (8 warps, 16 queries each).
// Output: split bf16 hi/lo [B,L,D] for the out-projection GEMM.
// ---------------------------------------------------------------------------
#define ASTR     72
#define A_STAGES 3

struct AttnStage {
    __half Ks[64 * ASTR];
    __half Vs[64 * ASTR];
    int    Ms[64];
};
#define A_SMEM (A_STAGES * (int)sizeof(AttnStage))

__global__ __launch_bounds__(256, 2)
void attn_mma_kernel(const __half* __restrict__ Qh, const __half* __restrict__ Kh,
                     const __half* __restrict__ Vh, const int* __restrict__ kv_mask,
                     __nv_bfloat16* __restrict__ OutH,
                     __nv_bfloat16* __restrict__ OutL)
{
    extern __shared__ char asm_raw[];
    AttnStage* stg = (AttnStage*)asm_raw;

    const int tid  = threadIdx.x;
    const int lane = tid & 31;
    const int wid  = tid >> 5;
    const int bh   = blockIdx.y;
    const int b    = bh >> 4;
    const int h    = bh & 15;
    const int q0   = blockIdx.x * 128 + wid * 16;

    const __half* Kb = Kh + (size_t)bh * SEQ * HEAD_DIM;
    const __half* Vb = Vh + (size_t)bh * SEQ * HEAD_DIM;
    const int*    Mb = kv_mask + b * SEQ;

#define A_ISSUE(J0, ST)                                                        \
    do {                                                                       \
        uint32_t sK_ = smem_cast(stg[ST].Ks);                                  \
        uint32_t sV_ = smem_cast(stg[ST].Vs);                                  \
        uint32_t sM_ = smem_cast(stg[ST].Ms);                                  \
        for (int idx = tid; idx < 1040; idx += 256) {                          \
            if (idx < 512) {                                                   \
                int rr = idx >> 3, cc = idx & 7;                               \
                cp16(sK_ + (uint32_t)(rr * ASTR + cc * 8) * 2,                 \
                     Kb + (size_t)((J0) + rr) * HEAD_DIM + cc * 8);            \
            } else if (idx < 1024) {                                           \
                int q = idx - 512, rr = q >> 3, cc = q & 7;                    \
                cp16(sV_ + (uint32_t)(rr * ASTR + cc * 8) * 2,                 \
                     Vb + (size_t)((J0) + rr) * HEAD_DIM + cc * 8);            \
            } else {                                                           \
                int q = idx - 1024;                                            \
                cp16(sM_ + (uint32_t)q * 16, Mb + (J0) + q * 4);               \
            }                                                                  \
        }                                                                      \
    } while (0)

    // prologue: stages 0,1
    A_ISSUE(0, 0);  cp_commit();
    A_ISSUE(64, 1); cp_commit();

    // Q fragments (already scaled, fp16 in global)
    uint32_t aq[4][4];
    {
        const __half* Qb = Qh + (size_t)bh * SEQ * HEAD_DIM;
#pragma unroll
        for (int ks = 0; ks < 4; ++ks)
#pragma unroll
            for (int j = 0; j < 4; ++j) {
                const int rr = q0 + (lane >> 2) + (j & 1) * 8;
                const int cc = ks * 16 + ((j >> 1) << 3) + ((lane & 3) << 1);
                aq[ks][j] = *(const uint32_t*)&Qb[(size_t)rr * HEAD_DIM + cc];
            }
    }

    float O[8][4];
#pragma unroll
    for (int i = 0; i < 8; ++i)
#pragma unroll
        for (int j = 0; j < 4; ++j) O[i][j] = 0.0f;
    float m0r = -1e30f, m1r = -1e30f, l0r = 0.0f, l1r = 0.0f;

    // ldmatrix fragment offsets (bytes, within Ks/Vs)
    const uint32_t kfrag =
        (uint32_t)(((((lane >> 4) << 3) + (lane & 7)) * ASTR + ((lane >> 3) & 1) * 8)) * 2;
    const uint32_t vfrag =
        (uint32_t)((((((lane >> 3) & 1) << 3) + (lane & 7)) * ASTR + (lane >> 4) * 8)) * 2;

    const int NT = SEQ / 64;   // 32
    for (int kt = 0; kt < NT; ++kt) {
        cp_wait<1>();
        __syncthreads();
        if (kt + 2 < NT) A_ISSUE((kt + 2) * 64, (kt + 2) % A_STAGES);
        cp_commit();

        AttnStage* st = &stg[kt % A_STAGES];
        const uint32_t aK = smem_cast(st->Ks);
        const uint32_t aV = smem_cast(st->Vs);

        // ---- S = Q @ K^T ----
        float S[8][4];
#pragma unroll
        for (int i = 0; i < 8; ++i)
#pragma unroll
            for (int j = 0; j < 4; ++j) S[i][j] = 0.0f;
#pragma unroll
        for (int ks = 0; ks < 4; ++ks) {
#pragma unroll
            for (int p = 0; p < 4; ++p) {
                uint32_t bq[4];
                ldsm4(bq[0], bq[1], bq[2], bq[3],
                      aK + kfrag + (uint32_t)(p * 16 * ASTR * 2 + ks * 32));
                mma_f16(S[2 * p],     aq[ks], bq[0], bq[1]);
                mma_f16(S[2 * p + 1], aq[ks], bq[2], bq[3]);
            }
        }

        // ---- mask + row max ----
        float mx0 = -1e30f, mx1 = -1e30f;
#pragma unroll
        for (int nt = 0; nt < 8; ++nt) {
            const int kk = nt * 8 + ((lane & 3) << 1);
            const int2 mi = *(const int2*)&st->Ms[kk];
            const float mdx = mi.x ? 0.0f : -1e30f;
            const float mdy = mi.y ? 0.0f : -1e30f;
            S[nt][0] += mdx; S[nt][1] += mdy;
            S[nt][2] += mdx; S[nt][3] += mdy;
            mx0 = fmaxf(mx0, fmaxf(S[nt][0], S[nt][1]));
            mx1 = fmaxf(mx1, fmaxf(S[nt][2], S[nt][3]));
        }
        mx0 = fmaxf(mx0, __shfl_xor_sync(0xffffffffu, mx0, 1));
        mx0 = fmaxf(mx0, __shfl_xor_sync(0xffffffffu, mx0, 2));
        mx1 = fmaxf(mx1, __shfl_xor_sync(0xffffffffu, mx1, 1));
        mx1 = fmaxf(mx1, __shfl_xor_sync(0xffffffffu, mx1, 2));

        const float nm0 = fmaxf(m0r, mx0), nm1 = fmaxf(m1r, mx1);
        const float f0 = __expf(m0r - nm0), f1 = __expf(m1r - nm1);
        m0r = nm0; m1r = nm1;

        float s0 = 0.0f, s1 = 0.0f;
#pragma unroll
        for (int nt = 0; nt < 8; ++nt) {
            S[nt][0] = __expf(S[nt][0] - nm0);
            S[nt][1] = __expf(S[nt][1] - nm0);
            S[nt][2] = __expf(S[nt][2] - nm1);
            S[nt][3] = __expf(S[nt][3] - nm1);
            s0 += S[nt][0] + S[nt][1];
            s1 += S[nt][2] + S[nt][3];
        }
        s0 += __shfl_xor_sync(0xffffffffu, s0, 1);
        s0 += __shfl_xor_sync(0xffffffffu, s0, 2);
        s1 += __shfl_xor_sync(0xffffffffu, s1, 1);
        s1 += __shfl_xor_sync(0xffffffffu, s1, 2);
        l0r = l0r * f0 + s0;
        l1r = l1r * f1 + s1;

#pragma unroll
        for (int nt = 0; nt < 8; ++nt) {
            O[nt][0] *= f0; O[nt][1] *= f0;
            O[nt][2] *= f1; O[nt][3] *= f1;
        }

        // ---- O += P @ V ----
#pragma unroll
        for (int ks = 0; ks < 4; ++ks) {
            uint32_t pa[4];
            {
                __half2 t0 = __floats2half2_rn(S[2 * ks][0],     S[2 * ks][1]);
                __half2 t1 = __floats2half2_rn(S[2 * ks][2],     S[2 * ks][3]);
                __half2 t2 = __floats2half2_rn(S[2 * ks + 1][0], S[2 * ks + 1][1]);
                __half2 t3 = __floats2half2_rn(S[2 * ks + 1][2], S[2 * ks + 1][3]);
                pa[0] = *(uint32_t*)&t0; pa[1] = *(uint32_t*)&t1;
                pa[2] = *(uint32_t*)&t2; pa[3] = *(uint32_t*)&t3;
            }
#pragma unroll
            for (int p = 0; p < 4; ++p) {
                uint32_t bv[4];
                ldsm4t(bv[0], bv[1], bv[2], bv[3],
                       aV + vfrag + (uint32_t)(ks * 16 * ASTR * 2 + p * 32));
                mma_f16(O[2 * p],     pa, bv[0], bv[1]);
                mma_f16(O[2 * p + 1], pa, bv[2], bv[3]);
            }
        }
    }
#undef A_ISSUE

    // ---- normalize + split-bf16 store to [B,L,D] ----
    const float inv0 = 1.0f / l0r, inv1 = 1.0f / l1r;
    const int qr = q0 + (lane >> 2);
    const size_t base0 = ((size_t)b * SEQ + qr) * DIMN + h * HEAD_DIM;
    const size_t base1 = ((size_t)b * SEQ + qr + 8) * DIMN + h * HEAD_DIM;
#pragma unroll
    for (int nt = 0; nt < 8; ++nt) {
        const int c = nt * 8 + ((lane & 3) << 1);
        __nv_bfloat162 h0, l0, h1, l1;
        split2(O[nt][0] * inv0, O[nt][1] * inv0, h0, l0);
        split2(O[nt][2] * inv1, O[nt][3] * inv1, h1, l1);
        *(__nv_bfloat162*)&OutH[base0 + c] = h0;
        *(__nv_bfloat162*)&OutL[base0 + c] = l0;
        *(__nv_bfloat162*)&OutH[base1 + c] = h1;
        *(__nv_bfloat162*)&OutL[base1 + c] = l1;
    }
}

// ---------------------------------------------------------------------------
extern "C" void kernel_launch(void* const* d_in, const int* in_sizes, int n_in,
                              void* d_out, int out_size)
{
    const float* q    = (const float*)d_in[0];
    const float* k    = (const float*)d_in[1];
    const float* v    = (const float*)d_in[2];
    const int*   mask = (const int*)  d_in[3];
    const float* Wq   = (const float*)d_in[4];
    const float* bq   = (const float*)d_in[5];
    const float* Wk   = (const float*)d_in[6];
    const float* bk   = (const float*)d_in[7];
    const float* Wv   = (const float*)d_in[8];
    const float* bv   = (const float*)d_in[9];
    const float* Wo   = (const float*)d_in[10];
    const float* bo   = (const float*)d_in[11];
    float*       out  = (float*)d_out;

    static bool attr_done = false;
    if (!attr_done) {
        cudaFuncSetAttribute(gemm_ts_kernel,
                             cudaFuncAttributeMaxDynamicSharedMemorySize, G_SMEM);
        cudaFuncSetAttribute(attn_mma_kernel,
                             cudaFuncAttributeMaxDynamicSharedMemorySize, A_SMEM);
        attr_done = true;
    }

    void *p_xh, *p_xl, *p_wh, *p_wl, *p_q16, *p_k16, *p_v16, *p_ah, *p_al;
    cudaGetSymbolAddress(&p_xh,  g_xh);
    cudaGetSymbolAddress(&p_xl,  g_xl);
    cudaGetSymbolAddress(&p_wh,  g_wh);
    cudaGetSymbolAddress(&p_wl,  g_wl);
    cudaGetSymbolAddress(&p_q16, g_q16);
    cudaGetSymbolAddress(&p_k16, g_k16);
    cudaGetSymbolAddress(&p_v16, g_v16);
    cudaGetSymbolAddress(&p_ah,  g_ah);
    cudaGetSymbolAddress(&p_al,  g_al);

    __nv_bfloat16* xh = (__nv_bfloat16*)p_xh;
    __nv_bfloat16* xl = (__nv_bfloat16*)p_xl;
    __nv_bfloat16* wh = (__nv_bfloat16*)p_wh;
    __nv_bfloat16* wl = (__nv_bfloat16*)p_wl;

    // split inputs (3 x 4M) and weights (4 x 1M)
    split_kernel<<<dim3(NELEM / 1024, 3), 256>>>(q, k, v, nullptr, xh, xl, NELEM);
    split_kernel<<<dim3(WELEM / 1024, 4), 256>>>(Wq, Wk, Wv, Wo, wh, wl, WELEM);

    dim3 gg(DIMN / 128, MROWS / 128);   // (8, 32)
    gemm_ts_kernel<<<gg, 256, G_SMEM>>>(xh, xl, wh, wl, bq,
                                        (__half*)p_q16, nullptr, QK_SCALE, 0);
    gemm_ts_kernel<<<gg, 256, G_SMEM>>>(xh + (size_t)NELEM, xl + (size_t)NELEM,
                                        wh + (size_t)WELEM, wl + (size_t)WELEM, bk,
                                        (__half*)p_k16, nullptr, 1.0f, 0);
    gemm_ts_kernel<<<gg, 256, G_SMEM>>>(xh + 2 * (size_t)NELEM, xl + 2 * (size_t)NELEM,
                                        wh + 2 * (size_t)WELEM, wl + 2 * (size_t)WELEM, bv,
                                        (__half*)p_v16, nullptr, 1.0f, 0);

    dim3 ag(SEQ / 128, BATCH * NUM_HEADS);   // (16, 32)
    attn_mma_kernel<<<ag, 256, A_SMEM>>>((const __half*)p_q16, (const __half*)p_k16,
                                         (const __half*)p_v16, mask,
                                         (__nv_bfloat16*)p_ah, (__nv_bfloat16*)p_al);

    gemm_ts_kernel<<<gg, 256, G_SMEM>>>((__nv_bfloat16*)p_ah, (__nv_bfloat16*)p_al,
                                        wh + 3 * (size_t)WELEM, wl + 3 * (size_t)WELEM, bo,
                                        nullptr, out, 1.0f, 1);
}